// round 2
// baseline (speedup 1.0000x reference)
#include <cuda_runtime.h>
#include <math.h>

// ---------------- constants ----------------
// B=2, S=2048, H=4096, NH=32, NKV=2, HD=128, ROT=64
// BS = B*S = 4096 tokens
// qkv width = (NH + 2*NKV)*HD = 36*128 = 4608
//   q: cols [0, 4096), k: cols [4096, 4352), v: cols [4352, 4608)

__device__ float g_qkv[(size_t)4096 * 4608];   // 75.5 MB scratch
__device__ float g_attn[(size_t)4096 * 4096];  // 67 MB scratch

// ---------------- SGEMM: C[M,N] = A[M,K] @ B[K,N] (+bias) ----------------
// 128x128 block tile, K-step 8, 256 threads, 8x8 per-thread micro-tile.
__global__ __launch_bounds__(256, 2)
void sgemm_kernel(const float* __restrict__ A, const float* __restrict__ B,
                  const float* __restrict__ bias, float* __restrict__ C,
                  int M, int N, int K)
{
    __shared__ float As[8][128];
    __shared__ float Bs[8][128];

    const int tid = threadIdx.x;
    const int tx = tid & 15;       // 0..15
    const int ty = tid >> 4;       // 0..15
    const int bx = blockIdx.x;
    const int by = blockIdx.y;

    const int rowA = tid >> 1;          // 0..127
    const int segA = (tid & 1) << 2;    // 0 or 4
    const int rowB = tid >> 5;          // 0..7
    const int colB = (tid & 31) << 2;   // 0..124

    float acc[8][8];
#pragma unroll
    for (int i = 0; i < 8; i++)
#pragma unroll
        for (int j = 0; j < 8; j++) acc[i][j] = 0.f;

    const float* Aptr = A + (size_t)(by * 128 + rowA) * K + segA;
    const float* Bptr = B + (size_t)rowB * N + bx * 128 + colB;

    for (int k0 = 0; k0 < K; k0 += 8) {
        float4 a4 = *(const float4*)(Aptr + k0);
        As[segA + 0][rowA] = a4.x;
        As[segA + 1][rowA] = a4.y;
        As[segA + 2][rowA] = a4.z;
        As[segA + 3][rowA] = a4.w;
        float4 b4 = *(const float4*)(Bptr + (size_t)k0 * N);
        *(float4*)&Bs[rowB][colB] = b4;
        __syncthreads();

#pragma unroll
        for (int kk = 0; kk < 8; kk++) {
            float4 a0 = *(const float4*)&As[kk][ty * 8];
            float4 a1 = *(const float4*)&As[kk][ty * 8 + 4];
            float4 b0 = *(const float4*)&Bs[kk][tx * 8];
            float4 b1 = *(const float4*)&Bs[kk][tx * 8 + 4];
            float a[8] = {a0.x, a0.y, a0.z, a0.w, a1.x, a1.y, a1.z, a1.w};
            float b[8] = {b0.x, b0.y, b0.z, b0.w, b1.x, b1.y, b1.z, b1.w};
#pragma unroll
            for (int i = 0; i < 8; i++)
#pragma unroll
                for (int j = 0; j < 8; j++)
                    acc[i][j] = fmaf(a[i], b[j], acc[i][j]);
        }
        __syncthreads();
    }

#pragma unroll
    for (int i = 0; i < 8; i++) {
        int r = by * 128 + ty * 8 + i;
        int cbase = bx * 128 + tx * 8;
        float* Crow = C + (size_t)r * N + cbase;
#pragma unroll
        for (int j = 0; j < 8; j++) {
            float v = acc[i][j];
            if (bias) v += bias[cbase + j];
            Crow[j] = v;
        }
    }
}

// ---------------- RoPE (interleaved-pair GLM rope on first 64 dims) -------
// heads 0..31 -> q heads (cols h*128), heads 32..33 -> k heads (cols 4096+)
__global__ void rope_kernel(float* __restrict__ qkv, const int* __restrict__ positions)
{
    int idx = blockIdx.x * blockDim.x + threadIdx.x;
    const int total = 4096 * 34 * 32;
    if (idx >= total) return;
    int i = idx & 31;                 // rotation pair index 0..31
    int head = (idx >> 5) % 34;       // 0..33
    int token = idx / (34 * 32);      // 0..4095
    int pos = positions[token];

    // inv_freq = 10000^(-i/32) = exp(-i * ln(10000)/32)
    float inv = expf((float)(-i) * 0.28782313662425572f);
    float ang = (float)pos * inv;
    float c, s;
    sincosf(ang, &s, &c);

    float* p = qkv + (size_t)token * 4608 + head * 128 + 2 * i;
    float x1 = p[0], x2 = p[1];
    p[0] = x1 * c - x2 * s;
    p[1] = x1 * s + x2 * c;
}

// ---------------- Flash attention (causal, GQA G=16) ----------------------
// Block: 256 threads, one (q-tile of 64) x (head) x (batch).
// Online softmax over 64-key tiles; only tiles kt <= qt are visited.
struct AttnSmem {
    float4 Q[64][33];
    float4 K[64][33];
    float4 V[64][33];
    float  S[64][65];
    float  m[64];
    float  l[64];
    float  sf[64];
};

__global__ __launch_bounds__(256, 1)
void attn_kernel(const float* __restrict__ qkv, float* __restrict__ out)
{
    extern __shared__ char smem_raw[];
    AttnSmem* sm = reinterpret_cast<AttnSmem*>(smem_raw);
    const int tid = threadIdx.x;
    const int qt = blockIdx.x;   // 0..31 (query tile)
    const int h  = blockIdx.y;   // 0..31 (q head)
    const int b  = blockIdx.z;   // 0..1
    const int kvh = h >> 4;      // G = 16
    const int bS = b * 2048;
    const int qcol = h * 128;
    const int kcol = 4096 + kvh * 128;
    const int vcol = 4352 + kvh * 128;

    // load Q tile
    for (int idx = tid; idx < 64 * 32; idx += 256) {
        int r = idx >> 5, d4 = idx & 31;
        size_t row = (size_t)(bS + qt * 64 + r) * 4608;
        sm->Q[r][d4] = *(const float4*)(qkv + row + qcol + d4 * 4);
    }
    if (tid < 64) { sm->m[tid] = -INFINITY; sm->l[tid] = 0.f; }

    // score micro-tile ownership: 4 queries x 4 keys
    const int sy = tid >> 4;   // 0..15
    const int sx = tid & 15;   // 0..15
    // PV ownership: 4 queries x 8 dims
    const int qg = tid >> 4;   // 0..15 (queries qg*4..+4)
    const int dg = tid & 15;   // dims dg*8..+8

    float4 acc[4][2];
#pragma unroll
    for (int i = 0; i < 4; i++)
#pragma unroll
        for (int j = 0; j < 2; j++) acc[i][j] = make_float4(0.f, 0.f, 0.f, 0.f);

    const float scale = 0.08838834764831845f;  // 128^-0.5
    __syncthreads();

    for (int kt = 0; kt <= qt; kt++) {
        // load K, V tiles
        for (int idx = tid; idx < 64 * 32; idx += 256) {
            int r = idx >> 5, d4 = idx & 31;
            size_t row = (size_t)(bS + kt * 64 + r) * 4608;
            sm->K[r][d4] = *(const float4*)(qkv + row + kcol + d4 * 4);
            sm->V[r][d4] = *(const float4*)(qkv + row + vcol + d4 * 4);
        }
        __syncthreads();

        // scores
        float s[4][4];
#pragma unroll
        for (int i = 0; i < 4; i++)
#pragma unroll
            for (int j = 0; j < 4; j++) s[i][j] = 0.f;

#pragma unroll 4
        for (int d4 = 0; d4 < 32; d4++) {
            float4 a[4], bb[4];
#pragma unroll
            for (int i = 0; i < 4; i++) a[i] = sm->Q[sy * 4 + i][d4];
#pragma unroll
            for (int j = 0; j < 4; j++) bb[j] = sm->K[sx * 4 + j][d4];
#pragma unroll
            for (int i = 0; i < 4; i++)
#pragma unroll
                for (int j = 0; j < 4; j++) {
                    s[i][j] = fmaf(a[i].x, bb[j].x, s[i][j]);
                    s[i][j] = fmaf(a[i].y, bb[j].y, s[i][j]);
                    s[i][j] = fmaf(a[i].z, bb[j].z, s[i][j]);
                    s[i][j] = fmaf(a[i].w, bb[j].w, s[i][j]);
                }
        }
        const bool diag = (kt == qt);
#pragma unroll
        for (int i = 0; i < 4; i++)
#pragma unroll
            for (int j = 0; j < 4; j++) {
                int q = sy * 4 + i, k = sx * 4 + j;
                float v = s[i][j] * scale;
                if (diag && k > q) v = -INFINITY;
                sm->S[q][k] = v;
            }
        __syncthreads();

        // online softmax row update (one thread per query row)
        if (tid < 64) {
            float mold = sm->m[tid];
            float mx = mold;
            float* Srow = sm->S[tid];
#pragma unroll 8
            for (int t = 0; t < 64; t++) mx = fmaxf(mx, Srow[t]);
            float f = expf(mold - mx);
            float lsum = sm->l[tid] * f;
#pragma unroll 8
            for (int t = 0; t < 64; t++) {
                float e = expf(Srow[t] - mx);
                Srow[t] = e;
                lsum += e;
            }
            sm->m[tid] = mx;
            sm->l[tid] = lsum;
            sm->sf[tid] = f;
        }
        __syncthreads();

        // rescale accumulators + P@V
#pragma unroll
        for (int i = 0; i < 4; i++) {
            float f = sm->sf[qg * 4 + i];
#pragma unroll
            for (int j = 0; j < 2; j++) {
                acc[i][j].x *= f; acc[i][j].y *= f;
                acc[i][j].z *= f; acc[i][j].w *= f;
            }
        }
#pragma unroll 2
        for (int t = 0; t < 64; t++) {
            float4 v0 = sm->V[t][dg * 2];
            float4 v1 = sm->V[t][dg * 2 + 1];
#pragma unroll
            for (int i = 0; i < 4; i++) {
                float p = sm->S[qg * 4 + i][t];
                acc[i][0].x = fmaf(p, v0.x, acc[i][0].x);
                acc[i][0].y = fmaf(p, v0.y, acc[i][0].y);
                acc[i][0].z = fmaf(p, v0.z, acc[i][0].z);
                acc[i][0].w = fmaf(p, v0.w, acc[i][0].w);
                acc[i][1].x = fmaf(p, v1.x, acc[i][1].x);
                acc[i][1].y = fmaf(p, v1.y, acc[i][1].y);
                acc[i][1].z = fmaf(p, v1.z, acc[i][1].z);
                acc[i][1].w = fmaf(p, v1.w, acc[i][1].w);
            }
        }
        __syncthreads();
    }

    // epilogue: out[b, s, h*128 + d] = acc / l
#pragma unroll
    for (int i = 0; i < 4; i++) {
        int q = qg * 4 + i;
        float inv = 1.0f / sm->l[q];
        int grow = bS + qt * 64 + q;
        float* op = out + (size_t)grow * 4096 + h * 128 + dg * 8;
        float4 o0 = acc[i][0], o1 = acc[i][1];
        o0.x *= inv; o0.y *= inv; o0.z *= inv; o0.w *= inv;
        o1.x *= inv; o1.y *= inv; o1.z *= inv; o1.w *= inv;
        *(float4*)op = o0;
        *(float4*)(op + 4) = o1;
    }
}

// ---------------- launch ----------------
extern "C" void kernel_launch(void* const* d_in, const int* in_sizes, int n_in,
                              void* d_out, int out_size)
{
    const float* hidden   = (const float*)d_in[0];  // [4096, 4096]
    const float* w_qkv    = (const float*)d_in[1];  // [4096, 4608]
    const float* b_qkv    = (const float*)d_in[2];  // [4608]
    const float* w_dense  = (const float*)d_in[3];  // [4096, 4096]
    const int*   positions = (const int*)d_in[4];   // [2, 2048]
    float* out = (float*)d_out;                     // [4096, 4096]

    float* qkv = nullptr;
    float* attn = nullptr;
    cudaGetSymbolAddress((void**)&qkv, g_qkv);
    cudaGetSymbolAddress((void**)&attn, g_attn);

    // 1) QKV projection + bias
    sgemm_kernel<<<dim3(4608 / 128, 4096 / 128), 256>>>(
        hidden, w_qkv, b_qkv, qkv, 4096, 4608, 4096);

    // 2) RoPE on q (32 heads) and k (2 heads)
    {
        int total = 4096 * 34 * 32;
        rope_kernel<<<(total + 255) / 256, 256>>>(qkv, positions);
    }

    // 3) causal GQA flash attention
    cudaFuncSetAttribute(attn_kernel, cudaFuncAttributeMaxDynamicSharedMemorySize,
                         (int)sizeof(AttnSmem));
    attn_kernel<<<dim3(32, 32, 2), 256, sizeof(AttnSmem)>>>(qkv, attn);

    // 4) dense output projection
    sgemm_kernel<<<dim3(4096 / 128, 4096 / 128), 256>>>(
        attn, w_dense, nullptr, out, 4096, 4096, 4096);
}

// round 4
// speedup vs baseline: 1.6243x; 1.6243x over previous
#include <cuda_runtime.h>
#include <math.h>
#include <stdint.h>

// ---------------- constants ----------------
// B=2, S=2048, H=4096, NH=32, NKV=2, HD=128, ROT=64
// BS = B*S = 4096 tokens; qkv width = 36*128 = 4608
//   q: cols [0,4096), k: [4096,4352), v: [4352,4608)

__device__ float g_qkv[(size_t)4096 * 4608];
__device__ float g_attn[(size_t)4096 * 4096];
__device__ float g_hid[(size_t)4096 * 4096];     // rna-rounded hidden
__device__ float g_wqkvT[(size_t)4608 * 4096];   // w_qkv^T, rna-rounded
__device__ float g_wdenseT[(size_t)4096 * 4096]; // w_dense^T, rna-rounded

// ---------------- helpers ----------------
__device__ __forceinline__ float rna_tf32(float x) {
    float y;
    asm("cvt.rna.tf32.f32 %0, %1;" : "=f"(y) : "f"(x));
    return y;
}

__device__ __forceinline__ uint32_t smem_u32(const void* p) {
    uint32_t a;
    asm("{ .reg .u64 t; cvta.to.shared.u64 t, %1; cvt.u32.u64 %0, t; }" : "=r"(a) : "l"(p));
    return a;
}

__device__ __forceinline__ void cp16(uint32_t s, const void* g) {
    asm volatile("cp.async.cg.shared.global [%0], [%1], 16;" :: "r"(s), "l"(g));
}

__device__ __forceinline__ void mma_tf32(float* d, const uint32_t* a, const uint32_t* b) {
    asm volatile(
        "mma.sync.aligned.m16n8k8.row.col.f32.tf32.tf32.f32 "
        "{%0,%1,%2,%3}, {%4,%5,%6,%7}, {%8,%9}, {%0,%1,%2,%3};"
        : "+f"(d[0]), "+f"(d[1]), "+f"(d[2]), "+f"(d[3])
        : "r"(a[0]), "r"(a[1]), "r"(a[2]), "r"(a[3]), "r"(b[0]), "r"(b[1]));
}

// ---------------- TF32 mma.sync GEMM ----------------
// C[M,N] = A[M,K] @ Bt[N,K]^T (+bias). A,Bt pre-rounded to tf32.
// CTA tile 128x128, K-chunk 32, 256 thr / 8 warps, warp tile 32x64.
// Smem tiles K-major with stride 36 floats (conflict-free frag loads).
#define GS 3
#define CHUNK_FLOATS 4608               // 128*36
#define STAGE_FLOATS 9216               // A + B
#define G_SMEM_BYTES (GS * STAGE_FLOATS * 4)   // 110592

__global__ __launch_bounds__(256, 2)
void gemm_tf32(const float* __restrict__ A, const float* __restrict__ Bt,
               const float* __restrict__ bias, float* __restrict__ C,
               int M, int N, int K)
{
    extern __shared__ float sm[];
    const uint32_t sb = smem_u32(sm);
    const int tid = threadIdx.x;
    const int wid = tid >> 5, lane = tid & 31;
    const int grp = lane >> 2, thr = lane & 3;
    const int wm = wid & 3, wn = wid >> 2;
    const int m0 = blockIdx.y * 128;
    const int n0 = blockIdx.x * 128;

    // global->smem: row = tid>>1 (0..127), half = tid&1 covers 16 floats
    const int grow = tid >> 1;
    const int half = tid & 1;
    const float* Ap = A + (size_t)(m0 + grow) * K + half * 16;
    const float* Bp = Bt + (size_t)(n0 + grow) * K + half * 16;
    const uint32_t sdst = sb + (uint32_t)grow * 144 + (uint32_t)half * 64;

    auto load_stage = [&](int ch, int st) {
        const uint32_t so = (uint32_t)st * (STAGE_FLOATS * 4);
        const float* a = Ap + ch * 32;
        const float* b = Bp + ch * 32;
#pragma unroll
        for (int i = 0; i < 4; i++) cp16(sdst + so + i * 16, a + i * 4);
#pragma unroll
        for (int i = 0; i < 4; i++) cp16(sdst + so + CHUNK_FLOATS * 4 + i * 16, b + i * 4);
        asm volatile("cp.async.commit_group;" ::: "memory");
    };

    float acc[2][8][4];
#pragma unroll
    for (int mt = 0; mt < 2; mt++)
#pragma unroll
        for (int nt = 0; nt < 8; nt++)
#pragma unroll
            for (int j = 0; j < 4; j++) acc[mt][nt][j] = 0.f;

    const int NK = K >> 5;   // 128
    load_stage(0, 0);
    load_stage(1, 1);

    const int aBase = (wm * 32 + grp) * 36 + thr;
    const int bBase = CHUNK_FLOATS + (wn * 64 + grp) * 36 + thr;

    int st = 0;
    for (int i = 0; i < NK; i++) {
        asm volatile("cp.async.wait_group %0;" :: "n"(1) : "memory");
        __syncthreads();
        int nxt = i + 2;
        if (nxt < NK) {
            int ns = st + 2; if (ns >= GS) ns -= GS;
            load_stage(nxt, ns);
        } else {
            asm volatile("cp.async.commit_group;" ::: "memory");
        }

        const float* As = sm + st * STAGE_FLOATS + aBase;
        const float* Bs = sm + st * STAGE_FLOATS + bBase;
#pragma unroll
        for (int k = 0; k < 4; k++) {
            const int ko = k * 8;
            uint32_t a[2][4], b[8][2];
#pragma unroll
            for (int mt = 0; mt < 2; mt++) {
                a[mt][0] = __float_as_uint(As[(mt * 16) * 36 + ko]);
                a[mt][1] = __float_as_uint(As[(mt * 16 + 8) * 36 + ko]);
                a[mt][2] = __float_as_uint(As[(mt * 16) * 36 + ko + 4]);
                a[mt][3] = __float_as_uint(As[(mt * 16 + 8) * 36 + ko + 4]);
            }
#pragma unroll
            for (int nt = 0; nt < 8; nt++) {
                b[nt][0] = __float_as_uint(Bs[nt * 8 * 36 + ko]);
                b[nt][1] = __float_as_uint(Bs[nt * 8 * 36 + ko + 4]);
            }
#pragma unroll
            for (int mt = 0; mt < 2; mt++)
#pragma unroll
                for (int nt = 0; nt < 8; nt++)
                    mma_tf32(acc[mt][nt], a[mt], b[nt]);
        }
        st++; if (st == GS) st = 0;
    }

    // epilogue
#pragma unroll
    for (int mt = 0; mt < 2; mt++) {
        const int r0 = m0 + wm * 32 + mt * 16 + grp;
#pragma unroll
        for (int nt = 0; nt < 8; nt++) {
            const int col = n0 + wn * 64 + nt * 8 + thr * 2;
            float b0 = 0.f, b1 = 0.f;
            if (bias) { b0 = __ldg(&bias[col]); b1 = __ldg(&bias[col + 1]); }
            float2 v0 = make_float2(acc[mt][nt][0] + b0, acc[mt][nt][1] + b1);
            float2 v1 = make_float2(acc[mt][nt][2] + b0, acc[mt][nt][3] + b1);
            *(float2*)&C[(size_t)r0 * N + col] = v0;
            *(float2*)&C[(size_t)(r0 + 8) * N + col] = v1;
        }
    }
}

// ---------------- operand prep ----------------
__global__ void rna_copy_kernel(const float4* __restrict__ src, float4* __restrict__ dst, int n4)
{
    int i = blockIdx.x * blockDim.x + threadIdx.x;
    if (i >= n4) return;
    float4 v = src[i];
    v.x = rna_tf32(v.x); v.y = rna_tf32(v.y);
    v.z = rna_tf32(v.z); v.w = rna_tf32(v.w);
    dst[i] = v;
}

__global__ void transpose_rna_kernel(const float* __restrict__ src, float* __restrict__ dst,
                                     int R, int C)
{
    __shared__ float t[32][33];
    int c0 = blockIdx.x * 32, r0 = blockIdx.y * 32;
    int x = threadIdx.x, y = threadIdx.y;  // 32 x 8
#pragma unroll
    for (int i = 0; i < 32; i += 8)
        t[y + i][x] = src[(size_t)(r0 + y + i) * C + c0 + x];
    __syncthreads();
#pragma unroll
    for (int i = 0; i < 32; i += 8)
        dst[(size_t)(c0 + y + i) * R + r0 + x] = rna_tf32(t[x][y + i]);
}

// ---------------- RoPE ----------------
__global__ void rope_kernel(float* __restrict__ qkv, const int* __restrict__ positions)
{
    int idx = blockIdx.x * blockDim.x + threadIdx.x;
    const int total = 4096 * 34 * 32;
    if (idx >= total) return;
    int i = idx & 31;
    int head = (idx >> 5) % 34;
    int token = idx / (34 * 32);
    int pos = positions[token];

    float inv = expf((float)(-i) * 0.28782313662425572f);
    float ang = (float)pos * inv;
    float c, s;
    sincosf(ang, &s, &c);

    float* p = qkv + (size_t)token * 4608 + head * 128 + 2 * i;
    float x1 = p[0], x2 = p[1];
    p[0] = x1 * c - x2 * s;
    p[1] = x1 * s + x2 * c;
}

// ---------------- Flash attention (causal, GQA G=16) ----------------
struct AttnSmem {
    float4 Q[64][33];
    float4 K[64][33];
    float4 V[64][33];
    float  S[64][65];
    float  m[64];
    float  l[64];
    float  sf[64];
};

__global__ __launch_bounds__(256, 1)
void attn_kernel(const float* __restrict__ qkv, float* __restrict__ out)
{
    extern __shared__ char smem_raw[];
    AttnSmem* sm = reinterpret_cast<AttnSmem*>(smem_raw);
    const int tid = threadIdx.x;
    const int qt = blockIdx.x;
    const int h  = blockIdx.y;
    const int b  = blockIdx.z;
    const int kvh = h >> 4;
    const int bS = b * 2048;
    const int qcol = h * 128;
    const int kcol = 4096 + kvh * 128;
    const int vcol = 4352 + kvh * 128;

    for (int idx = tid; idx < 64 * 32; idx += 256) {
        int r = idx >> 5, d4 = idx & 31;
        size_t row = (size_t)(bS + qt * 64 + r) * 4608;
        sm->Q[r][d4] = *(const float4*)(qkv + row + qcol + d4 * 4);
    }
    if (tid < 64) { sm->m[tid] = -INFINITY; sm->l[tid] = 0.f; }

    const int sy = tid >> 4;
    const int sx = tid & 15;
    const int qg = tid >> 4;
    const int dg = tid & 15;

    float4 acc[4][2];
#pragma unroll
    for (int i = 0; i < 4; i++)
#pragma unroll
        for (int j = 0; j < 2; j++) acc[i][j] = make_float4(0.f, 0.f, 0.f, 0.f);

    const float scale = 0.08838834764831845f;
    __syncthreads();

    for (int kt = 0; kt <= qt; kt++) {
        for (int idx = tid; idx < 64 * 32; idx += 256) {
            int r = idx >> 5, d4 = idx & 31;
            size_t row = (size_t)(bS + kt * 64 + r) * 4608;
            sm->K[r][d4] = *(const float4*)(qkv + row + kcol + d4 * 4);
            sm->V[r][d4] = *(const float4*)(qkv + row + vcol + d4 * 4);
        }
        __syncthreads();

        float s[4][4];
#pragma unroll
        for (int i = 0; i < 4; i++)
#pragma unroll
            for (int j = 0; j < 4; j++) s[i][j] = 0.f;

#pragma unroll 4
        for (int d4 = 0; d4 < 32; d4++) {
            float4 a[4], bb[4];
#pragma unroll
            for (int i = 0; i < 4; i++) a[i] = sm->Q[sy * 4 + i][d4];
#pragma unroll
            for (int j = 0; j < 4; j++) bb[j] = sm->K[sx * 4 + j][d4];
#pragma unroll
            for (int i = 0; i < 4; i++)
#pragma unroll
                for (int j = 0; j < 4; j++) {
                    s[i][j] = fmaf(a[i].x, bb[j].x, s[i][j]);
                    s[i][j] = fmaf(a[i].y, bb[j].y, s[i][j]);
                    s[i][j] = fmaf(a[i].z, bb[j].z, s[i][j]);
                    s[i][j] = fmaf(a[i].w, bb[j].w, s[i][j]);
                }
        }
        const bool diag = (kt == qt);
#pragma unroll
        for (int i = 0; i < 4; i++)
#pragma unroll
            for (int j = 0; j < 4; j++) {
                int q = sy * 4 + i, k = sx * 4 + j;
                float v = s[i][j] * scale;
                if (diag && k > q) v = -INFINITY;
                sm->S[q][k] = v;
            }
        __syncthreads();

        if (tid < 64) {
            float mold = sm->m[tid];
            float mx = mold;
            float* Srow = sm->S[tid];
#pragma unroll 8
            for (int t = 0; t < 64; t++) mx = fmaxf(mx, Srow[t]);
            float f = expf(mold - mx);
            float lsum = sm->l[tid] * f;
#pragma unroll 8
            for (int t = 0; t < 64; t++) {
                float e = expf(Srow[t] - mx);
                Srow[t] = e;
                lsum += e;
            }
            sm->m[tid] = mx;
            sm->l[tid] = lsum;
            sm->sf[tid] = f;
        }
        __syncthreads();

#pragma unroll
        for (int i = 0; i < 4; i++) {
            float f = sm->sf[qg * 4 + i];
#pragma unroll
            for (int j = 0; j < 2; j++) {
                acc[i][j].x *= f; acc[i][j].y *= f;
                acc[i][j].z *= f; acc[i][j].w *= f;
            }
        }
#pragma unroll 2
        for (int t = 0; t < 64; t++) {
            float4 v0 = sm->V[t][dg * 2];
            float4 v1 = sm->V[t][dg * 2 + 1];
#pragma unroll
            for (int i = 0; i < 4; i++) {
                float p = sm->S[qg * 4 + i][t];
                acc[i][0].x = fmaf(p, v0.x, acc[i][0].x);
                acc[i][0].y = fmaf(p, v0.y, acc[i][0].y);
                acc[i][0].z = fmaf(p, v0.z, acc[i][0].z);
                acc[i][0].w = fmaf(p, v0.w, acc[i][0].w);
                acc[i][1].x = fmaf(p, v1.x, acc[i][1].x);
                acc[i][1].y = fmaf(p, v1.y, acc[i][1].y);
                acc[i][1].z = fmaf(p, v1.z, acc[i][1].z);
                acc[i][1].w = fmaf(p, v1.w, acc[i][1].w);
            }
        }
        __syncthreads();
    }

    // epilogue: round to tf32 (feeds the tf32 dense GEMM)
#pragma unroll
    for (int i = 0; i < 4; i++) {
        int q = qg * 4 + i;
        float inv = 1.0f / sm->l[q];
        int grow = bS + qt * 64 + q;
        float* op = out + (size_t)grow * 4096 + h * 128 + dg * 8;
        float4 o0 = acc[i][0], o1 = acc[i][1];
        o0.x = rna_tf32(o0.x * inv); o0.y = rna_tf32(o0.y * inv);
        o0.z = rna_tf32(o0.z * inv); o0.w = rna_tf32(o0.w * inv);
        o1.x = rna_tf32(o1.x * inv); o1.y = rna_tf32(o1.y * inv);
        o1.z = rna_tf32(o1.z * inv); o1.w = rna_tf32(o1.w * inv);
        *(float4*)op = o0;
        *(float4*)(op + 4) = o1;
    }
}

// ---------------- launch ----------------
extern "C" void kernel_launch(void* const* d_in, const int* in_sizes, int n_in,
                              void* d_out, int out_size)
{
    const float* hidden    = (const float*)d_in[0];
    const float* w_qkv     = (const float*)d_in[1];
    const float* b_qkv     = (const float*)d_in[2];
    const float* w_dense   = (const float*)d_in[3];
    const int*   positions = (const int*)d_in[4];
    float* out = (float*)d_out;

    float *qkv, *attn, *hid, *wqkvT, *wdenseT;
    cudaGetSymbolAddress((void**)&qkv, g_qkv);
    cudaGetSymbolAddress((void**)&attn, g_attn);
    cudaGetSymbolAddress((void**)&hid, g_hid);
    cudaGetSymbolAddress((void**)&wqkvT, g_wqkvT);
    cudaGetSymbolAddress((void**)&wdenseT, g_wdenseT);

    cudaFuncSetAttribute(gemm_tf32, cudaFuncAttributeMaxDynamicSharedMemorySize,
                         G_SMEM_BYTES);
    cudaFuncSetAttribute(attn_kernel, cudaFuncAttributeMaxDynamicSharedMemorySize,
                         (int)sizeof(AttnSmem));

    // operand prep
    {
        int n4 = 4096 * 4096 / 4;
        rna_copy_kernel<<<(n4 + 255) / 256, 256>>>((const float4*)hidden, (float4*)hid, n4);
    }
    transpose_rna_kernel<<<dim3(4608 / 32, 4096 / 32), dim3(32, 8)>>>(w_qkv, wqkvT, 4096, 4608);
    transpose_rna_kernel<<<dim3(4096 / 32, 4096 / 32), dim3(32, 8)>>>(w_dense, wdenseT, 4096, 4096);

    // 1) QKV projection + bias
    gemm_tf32<<<dim3(4608 / 128, 4096 / 128), 256, G_SMEM_BYTES>>>(
        hid, wqkvT, b_qkv, qkv, 4096, 4608, 4096);

    // 2) RoPE
    {
        int total = 4096 * 34 * 32;
        rope_kernel<<<(total + 255) / 256, 256>>>(qkv, positions);
    }

    // 3) causal GQA flash attention
    attn_kernel<<<dim3(32, 32, 2), 256, sizeof(AttnSmem)>>>(qkv, attn);

    // 4) dense output projection
    gemm_tf32<<<dim3(4096 / 128, 4096 / 128), 256, G_SMEM_BYTES>>>(
        attn, wdenseT, nullptr, out, 4096, 4096, 4096);
}

// round 5
// speedup vs baseline: 6.9352x; 4.2696x over previous
#include <cuda_runtime.h>
#include <cuda_fp16.h>
#include <math.h>
#include <stdint.h>

// ---------------- constants ----------------
// B=2, S=2048, H=4096, NH=32, NKV=2, HD=128, ROT=64
// BS = 4096 tokens; qkv width = 36*128 = 4608 (q:[0,4096) k:[4096,4352) v:[4352,4608))

__device__ float  g_qkv[(size_t)4096 * 4608];      // fp32 qkv (accurate bias+rope base)
__device__ __half g_hid_h[(size_t)4096 * 4096];    // hidden fp16
__device__ __half g_wqkvT_h[(size_t)4608 * 4096];  // w_qkv^T fp16
__device__ __half g_wdenseT_h[(size_t)4096 * 4096];// w_dense^T fp16
__device__ __half g_q_h[(size_t)2 * 32 * 2048 * 128];  // [b][h][t][d], rope+scale
__device__ __half g_k_h[(size_t)2 * 2 * 2048 * 128];   // [b][kvh][t][d], rope
__device__ __half g_v_t[(size_t)2 * 2 * 128 * 2048];   // [b][kvh][d][t]  (transposed!)
__device__ __half g_attn_h[(size_t)4096 * 4096];   // attention out fp16 [tok][H]

// ---------------- helpers ----------------
__device__ __forceinline__ uint32_t smem_u32(const void* p) {
    uint32_t a;
    asm("{ .reg .u64 t; cvta.to.shared.u64 t, %1; cvt.u32.u64 %0, t; }" : "=r"(a) : "l"(p));
    return a;
}
__device__ __forceinline__ void cp16(uint32_t s, const void* g) {
    asm volatile("cp.async.cg.shared.global [%0], [%1], 16;" :: "r"(s), "l"(g));
}
__device__ __forceinline__ void mma_f16(float* d, const uint32_t* a, const uint32_t* b) {
    asm volatile(
        "mma.sync.aligned.m16n8k16.row.col.f32.f16.f16.f32 "
        "{%0,%1,%2,%3}, {%4,%5,%6,%7}, {%8,%9}, {%0,%1,%2,%3};"
        : "+f"(d[0]), "+f"(d[1]), "+f"(d[2]), "+f"(d[3])
        : "r"(a[0]), "r"(a[1]), "r"(a[2]), "r"(a[3]), "r"(b[0]), "r"(b[1]));
}
__device__ __forceinline__ uint32_t ldsm32(const __half* p) {
    return *(const uint32_t*)p;
}
__device__ __forceinline__ uint32_t packh2(float x, float y) {
    __half2 h = __floats2half2_rn(x, y);
    return *(uint32_t*)&h;
}

// ---------------- fp16 mma GEMM ----------------
// C[M,N] = A[M,K]h @ Bt[N,K]h^T (+bias fp32), fp32 out.
// CTA 128x128, K-chunk 32 halves, 3 stages, 256 thr, warp tile 32x64.
#define GS 3
#define STG_H 10240                       // halves per stage (A 5120 + B 5120)
#define G_SMEM_BYTES (GS * STG_H * 2)     // 61440

__global__ __launch_bounds__(256, 2)
void gemm_h(const __half* __restrict__ A, const __half* __restrict__ Bt,
            const float* __restrict__ bias, float* __restrict__ C,
            int M, int N, int K)
{
    extern __shared__ __half sh[];
    const uint32_t sb = smem_u32(sh);
    const int tid = threadIdx.x;
    const int wid = tid >> 5, lane = tid & 31;
    const int grp = lane >> 2, thr = lane & 3;
    const int wm = wid & 3, wn = wid >> 2;
    const int m0 = blockIdx.y * 128, n0 = blockIdx.x * 128;

    const int row = tid >> 1;            // 0..127
    const int off = (tid & 1) * 16;      // halves
    const __half* Ap = A + (size_t)(m0 + row) * K + off;
    const __half* Bp = Bt + (size_t)(n0 + row) * K + off;
    const uint32_t sA = sb + (uint32_t)(row * 40 + off) * 2;
    const uint32_t sB = sA + 5120 * 2;

    auto load_stage = [&](int ch, int st) {
        const uint32_t so = (uint32_t)st * (STG_H * 2);
        const __half* a = Ap + ch * 32;
        const __half* b = Bp + ch * 32;
        cp16(sA + so, a);        cp16(sA + so + 16, a + 8);
        cp16(sB + so, b);        cp16(sB + so + 16, b + 8);
        asm volatile("cp.async.commit_group;" ::: "memory");
    };

    float acc[2][8][4];
#pragma unroll
    for (int mt = 0; mt < 2; mt++)
#pragma unroll
        for (int nt = 0; nt < 8; nt++)
#pragma unroll
            for (int j = 0; j < 4; j++) acc[mt][nt][j] = 0.f;

    const int NK = K >> 5;   // chunks of 32 halves
    load_stage(0, 0);
    load_stage(1, 1);

    int st = 0;
    for (int i = 0; i < NK; i++) {
        asm volatile("cp.async.wait_group %0;" :: "n"(1) : "memory");
        __syncthreads();
        int nxt = i + 2;
        if (nxt < NK) {
            int ns = st + 2; if (ns >= GS) ns -= GS;
            load_stage(nxt, ns);
        } else {
            asm volatile("cp.async.commit_group;" ::: "memory");
        }

        const __half* As = sh + st * STG_H;
        const __half* Bs = As + 5120;
#pragma unroll
        for (int kk = 0; kk < 2; kk++) {
            const int ko = kk * 16 + thr * 2;
            uint32_t a[2][4], b[8][2];
#pragma unroll
            for (int mt = 0; mt < 2; mt++) {
                const __half* ar = As + (wm * 32 + mt * 16 + grp) * 40;
                a[mt][0] = ldsm32(ar + ko);
                a[mt][1] = ldsm32(ar + 8 * 40 + ko);
                a[mt][2] = ldsm32(ar + ko + 8);
                a[mt][3] = ldsm32(ar + 8 * 40 + ko + 8);
            }
#pragma unroll
            for (int nt = 0; nt < 8; nt++) {
                const __half* br = Bs + (wn * 64 + nt * 8 + grp) * 40;
                b[nt][0] = ldsm32(br + ko);
                b[nt][1] = ldsm32(br + ko + 8);
            }
#pragma unroll
            for (int mt = 0; mt < 2; mt++)
#pragma unroll
                for (int nt = 0; nt < 8; nt++)
                    mma_f16(acc[mt][nt], a[mt], b[nt]);
        }
        st++; if (st == GS) st = 0;
    }

#pragma unroll
    for (int mt = 0; mt < 2; mt++) {
        const int r0 = m0 + wm * 32 + mt * 16 + grp;
#pragma unroll
        for (int nt = 0; nt < 8; nt++) {
            const int col = n0 + wn * 64 + nt * 8 + thr * 2;
            float b0 = 0.f, b1 = 0.f;
            if (bias) { b0 = __ldg(&bias[col]); b1 = __ldg(&bias[col + 1]); }
            *(float2*)&C[(size_t)r0 * N + col] =
                make_float2(acc[mt][nt][0] + b0, acc[mt][nt][1] + b1);
            *(float2*)&C[(size_t)(r0 + 8) * N + col] =
                make_float2(acc[mt][nt][2] + b0, acc[mt][nt][3] + b1);
        }
    }
}

// ---------------- prep kernels ----------------
__global__ void convert_h_kernel(const float4* __restrict__ src, uint2* __restrict__ dst, int n4)
{
    int i = blockIdx.x * blockDim.x + threadIdx.x;
    if (i >= n4) return;
    float4 v = src[i];
    uint2 o;
    o.x = packh2(v.x, v.y);
    o.y = packh2(v.z, v.w);
    dst[i] = o;
}

// src [R][C] fp32 -> dst [C][R] fp16
__global__ void transpose_h_kernel(const float* __restrict__ src, __half* __restrict__ dst,
                                   int R, int C)
{
    __shared__ float t[32][33];
    int c0 = blockIdx.x * 32, r0 = blockIdx.y * 32;
    int x = threadIdx.x, y = threadIdx.y;  // 32 x 8
#pragma unroll
    for (int i = 0; i < 32; i += 8)
        t[y + i][x] = src[(size_t)(r0 + y + i) * C + c0 + x];
    __syncthreads();
#pragma unroll
    for (int i = 0; i < 32; i += 8)
        dst[(size_t)(c0 + y + i) * R + r0 + x] = __float2half(t[x][y + i]);
}

// rope + fp16 convert for q (heads 0..31, scaled) and k (heads 32,33)
__global__ void rope_convert_kernel(const float* __restrict__ qkv,
                                    const int* __restrict__ positions,
                                    __half* __restrict__ qh, __half* __restrict__ kh)
{
    int idx = blockIdx.x * blockDim.x + threadIdx.x;
    const int total = 4096 * 34 * 64;
    if (idx >= total) return;
    int i = idx & 63;                 // handles dims 2i, 2i+1
    int head = (idx >> 6) % 34;
    int tok = idx / (34 * 64);
    int b = tok >> 11, t = tok & 2047;

    const float* src = qkv + (size_t)tok * 4608 + head * 128;  // k heads: 32*128=4096 ✓
    float x1 = src[2 * i], x2 = src[2 * i + 1];
    if (i < 32) {
        int pos = positions[tok];
        float inv = __expf((float)(-i) * 0.28782313662425572f);
        float ang = (float)pos * inv;
        float c, s;
        __sincosf(ang, &s, &c);
        float o1 = x1 * c - x2 * s;
        float o2 = x1 * s + x2 * c;
        x1 = o1; x2 = o2;
    }
    uint32_t outp;
    if (head < 32) {
        const float scale = 0.08838834764831845f;
        outp = packh2(x1 * scale, x2 * scale);
        uint32_t* dst = (uint32_t*)(qh + ((((size_t)(b * 32 + head)) * 2048 + t) * 128 + 2 * i));
        *dst = outp;
    } else {
        outp = packh2(x1, x2);
        uint32_t* dst = (uint32_t*)(kh + ((((size_t)(b * 2 + head - 32)) * 2048 + t) * 128 + 2 * i));
        *dst = outp;
    }
}

// v transpose: qkv fp32 [tok][4352 + dglob] -> v_t fp16 [(b*256 + dglob)][2048]
__global__ void v_transpose_kernel(const float* __restrict__ qkv, __half* __restrict__ vt)
{
    __shared__ float t[32][33];
    int t0 = blockIdx.x * 32;       // token tile
    int d0 = blockIdx.y * 32;       // dglob tile (0..255)
    int b = blockIdx.z;
    int x = threadIdx.x, y = threadIdx.y;  // 32 x 8
#pragma unroll
    for (int i = 0; i < 32; i += 8)
        t[y + i][x] = qkv[(size_t)(b * 2048 + t0 + y + i) * 4608 + 4352 + d0 + x];
    __syncthreads();
#pragma unroll
    for (int i = 0; i < 32; i += 8)
        vt[(size_t)(b * 256 + d0 + y + i) * 2048 + t0 + x] = __float2half(t[x][y + i]);
}

// ---------------- fp16 mma flash attention ----------------
// grid (16 qtiles of 128, 32 heads, 2 batch), 256 thr / 8 warps.
// warp w owns q rows [w*16, w*16+16). KV tiles of 64 keys, double buffered.
// smem halves: Qs[128][136], Ks[2][64][136], Vt[2][128][72]
#define AQ_ST 136
#define AK_ST 136
#define AV_ST 72
#define SQ_OFF 0
#define SK_OFF (128 * AQ_ST)                      // 17408
#define SV_OFF (SK_OFF + 2 * 64 * AK_ST)          // 34816
#define A_SMEM_HALVES (SV_OFF + 2 * 128 * AV_ST)  // 53248
#define A_SMEM_BYTES (A_SMEM_HALVES * 2)          // 106496

__global__ __launch_bounds__(256, 1)
void attn_mma_kernel(const __half* __restrict__ qh, const __half* __restrict__ kh,
                     const __half* __restrict__ vt, __half* __restrict__ out)
{
    extern __shared__ __half sa[];
    const uint32_t sb = smem_u32(sa);
    const int tid = threadIdx.x;
    const int w = tid >> 5, lane = tid & 31;
    const int grp = lane >> 2, thr = lane & 3;
    const int qt = 15 - blockIdx.x;      // big tiles first
    const int h = blockIdx.y, b = blockIdx.z;
    const int kvh = h >> 4;

    const __half* Qg = qh + (((size_t)(b * 32 + h)) * 2048 + qt * 128) * 128;
    const __half* Kg = kh + ((size_t)(b * 2 + kvh)) * 2048 * 128;
    const __half* Vg = vt + ((size_t)(b * 2 + kvh)) * 128 * 2048;

    // Q load: 128 rows x 128 halves (16 cp16/row). thread: row=tid>>1, 8 cp16.
    {
        int r = tid >> 1;
        int s0 = (tid & 1) * 8;
        const __half* src = Qg + r * 128 + s0 * 8;
        uint32_t dst = sb + (uint32_t)(SQ_OFF + r * AQ_ST + s0 * 8) * 2;
#pragma unroll
        for (int j = 0; j < 8; j++) cp16(dst + j * 16, src + j * 8);
    }
    auto load_kv = [&](int kt, int buf) {
        // K: 64 rows x 128 halves. 4 thr/row, 4 cp16 each.
        {
            int r = tid >> 2;
            int s0 = (tid & 3) * 4;
            const __half* src = Kg + ((size_t)(kt * 64 + r)) * 128 + s0 * 8;
            uint32_t dst = sb + (uint32_t)(SK_OFF + buf * 64 * AK_ST + r * AK_ST + s0 * 8) * 2;
#pragma unroll
            for (int j = 0; j < 4; j++) cp16(dst + j * 16, src + j * 8);
        }
        // Vt: 128 rows (dims) x 64 halves (keys). 2 thr/row, 4 cp16 each.
        {
            int r = tid >> 1;
            int s0 = (tid & 1) * 4;
            const __half* src = Vg + (size_t)r * 2048 + kt * 64 + s0 * 8;
            uint32_t dst = sb + (uint32_t)(SV_OFF + buf * 128 * AV_ST + r * AV_ST + s0 * 8) * 2;
#pragma unroll
            for (int j = 0; j < 4; j++) cp16(dst + j * 16, src + j * 8);
        }
    };

    const int NT = 2 * qt + 2;
    load_kv(0, 0);
    asm volatile("cp.async.commit_group;" ::: "memory");

    float o[16][4];
#pragma unroll
    for (int nt = 0; nt < 16; nt++)
#pragma unroll
        for (int j = 0; j < 4; j++) o[nt][j] = 0.f;
    float m1 = -1e30f, m2 = -1e30f, l1 = 0.f, l2 = 0.f;

    const int qr1 = qt * 128 + w * 16 + grp;   // this lane's row 1 (within batch seq)
    const int qr2 = qr1 + 8;
    const int wr_max = qt * 128 + w * 16 + 15;

    for (int kt = 0; kt < NT; kt++) {
        if (kt + 1 < NT) load_kv(kt + 1, (kt + 1) & 1);
        asm volatile("cp.async.commit_group;" ::: "memory");
        asm volatile("cp.async.wait_group 1;" ::: "memory");
        __syncthreads();

        const bool active = (kt * 64 <= wr_max);
        if (active) {
            const __half* Ks = sa + SK_OFF + (kt & 1) * 64 * AK_ST;
            const __half* Vs = sa + SV_OFF + (kt & 1) * 128 * AV_ST;
            const __half* Qs = sa + SQ_OFF + (w * 16 + grp) * AQ_ST;

            float sc[8][4];
#pragma unroll
            for (int nt = 0; nt < 8; nt++)
#pragma unroll
                for (int j = 0; j < 4; j++) sc[nt][j] = 0.f;

#pragma unroll
            for (int kk = 0; kk < 8; kk++) {
                const int ko = kk * 16 + thr * 2;
                uint32_t aq[4];
                aq[0] = ldsm32(Qs + ko);
                aq[1] = ldsm32(Qs + 8 * AQ_ST + ko);
                aq[2] = ldsm32(Qs + ko + 8);
                aq[3] = ldsm32(Qs + 8 * AQ_ST + ko + 8);
#pragma unroll
                for (int nt = 0; nt < 8; nt++) {
                    uint32_t bk[2];
                    const __half* kr = Ks + (nt * 8 + grp) * AK_ST;
                    bk[0] = ldsm32(kr + ko);
                    bk[1] = ldsm32(kr + ko + 8);
                    mma_f16(sc[nt], aq, bk);
                }
            }

            // causal mask (only when tile reaches past the warp's min row)
            if (kt * 64 + 63 > qt * 128 + w * 16) {
#pragma unroll
                for (int nt = 0; nt < 8; nt++) {
                    int c0 = kt * 64 + nt * 8 + thr * 2;
                    if (c0 > qr1) sc[nt][0] = -1e30f;
                    if (c0 + 1 > qr1) sc[nt][1] = -1e30f;
                    if (c0 > qr2) sc[nt][2] = -1e30f;
                    if (c0 + 1 > qr2) sc[nt][3] = -1e30f;
                }
            }

            // row max
            float rm1 = -1e30f, rm2 = -1e30f;
#pragma unroll
            for (int nt = 0; nt < 8; nt++) {
                rm1 = fmaxf(rm1, fmaxf(sc[nt][0], sc[nt][1]));
                rm2 = fmaxf(rm2, fmaxf(sc[nt][2], sc[nt][3]));
            }
            rm1 = fmaxf(rm1, __shfl_xor_sync(0xffffffffu, rm1, 1));
            rm1 = fmaxf(rm1, __shfl_xor_sync(0xffffffffu, rm1, 2));
            rm2 = fmaxf(rm2, __shfl_xor_sync(0xffffffffu, rm2, 1));
            rm2 = fmaxf(rm2, __shfl_xor_sync(0xffffffffu, rm2, 2));

            float mn1 = fmaxf(m1, rm1), mn2 = fmaxf(m2, rm2);
            float f1 = __expf(m1 - mn1), f2 = __expf(m2 - mn2);
            m1 = mn1; m2 = mn2;

            // exp + pack P, partial row sums (per-lane)
            uint32_t pf[8][2];
            float s1 = 0.f, s2 = 0.f;
#pragma unroll
            for (int nt = 0; nt < 8; nt++) {
                float e0 = __expf(sc[nt][0] - mn1);
                float e1 = __expf(sc[nt][1] - mn1);
                float e2 = __expf(sc[nt][2] - mn2);
                float e3 = __expf(sc[nt][3] - mn2);
                s1 += e0 + e1; s2 += e2 + e3;
                pf[nt][0] = packh2(e0, e1);
                pf[nt][1] = packh2(e2, e3);
            }
            l1 = l1 * f1 + s1;
            l2 = l2 * f2 + s2;

            // rescale O
#pragma unroll
            for (int nt = 0; nt < 16; nt++) {
                o[nt][0] *= f1; o[nt][1] *= f1;
                o[nt][2] *= f2; o[nt][3] *= f2;
            }

            // P @ V  (A = P fragments in regs, B = V^T from smem)
#pragma unroll
            for (int kk = 0; kk < 4; kk++) {
                uint32_t ap[4] = {pf[2 * kk][0], pf[2 * kk][1],
                                  pf[2 * kk + 1][0], pf[2 * kk + 1][1]};
                const int ko = kk * 16 + thr * 2;
#pragma unroll
                for (int ntd = 0; ntd < 16; ntd++) {
                    uint32_t bv[2];
                    const __half* vr = Vs + (ntd * 8 + grp) * AV_ST;
                    bv[0] = ldsm32(vr + ko);
                    bv[1] = ldsm32(vr + ko + 8);
                    mma_f16(o[ntd], ap, bv);
                }
            }
        }
        __syncthreads();
    }

    // reduce l across the 4 lanes of each row group
    l1 += __shfl_xor_sync(0xffffffffu, l1, 1);
    l1 += __shfl_xor_sync(0xffffffffu, l1, 2);
    l2 += __shfl_xor_sync(0xffffffffu, l2, 1);
    l2 += __shfl_xor_sync(0xffffffffu, l2, 2);
    float inv1 = 1.f / l1, inv2 = 1.f / l2;

    const int row1 = b * 2048 + qr1;
    const int row2 = b * 2048 + qr2;
#pragma unroll
    for (int ntd = 0; ntd < 16; ntd++) {
        int col = h * 128 + ntd * 8 + thr * 2;
        *(uint32_t*)(out + (size_t)row1 * 4096 + col) = packh2(o[ntd][0] * inv1, o[ntd][1] * inv1);
        *(uint32_t*)(out + (size_t)row2 * 4096 + col) = packh2(o[ntd][2] * inv2, o[ntd][3] * inv2);
    }
}

// ---------------- launch ----------------
extern "C" void kernel_launch(void* const* d_in, const int* in_sizes, int n_in,
                              void* d_out, int out_size)
{
    const float* hidden    = (const float*)d_in[0];
    const float* w_qkv     = (const float*)d_in[1];
    const float* b_qkv     = (const float*)d_in[2];
    const float* w_dense   = (const float*)d_in[3];
    const int*   positions = (const int*)d_in[4];
    float* out = (float*)d_out;

    float* qkv; __half *hid_h, *wqkvT_h, *wdenseT_h, *q_h, *k_h, *v_t, *attn_h;
    cudaGetSymbolAddress((void**)&qkv, g_qkv);
    cudaGetSymbolAddress((void**)&hid_h, g_hid_h);
    cudaGetSymbolAddress((void**)&wqkvT_h, g_wqkvT_h);
    cudaGetSymbolAddress((void**)&wdenseT_h, g_wdenseT_h);
    cudaGetSymbolAddress((void**)&q_h, g_q_h);
    cudaGetSymbolAddress((void**)&k_h, g_k_h);
    cudaGetSymbolAddress((void**)&v_t, g_v_t);
    cudaGetSymbolAddress((void**)&attn_h, g_attn_h);

    cudaFuncSetAttribute(gemm_h, cudaFuncAttributeMaxDynamicSharedMemorySize, G_SMEM_BYTES);
    cudaFuncSetAttribute(attn_mma_kernel, cudaFuncAttributeMaxDynamicSharedMemorySize,
                         A_SMEM_BYTES);

    // prep: fp16 conversions
    {
        int n4 = 4096 * 4096 / 4;
        convert_h_kernel<<<(n4 + 255) / 256, 256>>>((const float4*)hidden, (uint2*)hid_h, n4);
    }
    transpose_h_kernel<<<dim3(4608 / 32, 4096 / 32), dim3(32, 8)>>>(w_qkv, wqkvT_h, 4096, 4608);
    transpose_h_kernel<<<dim3(4096 / 32, 4096 / 32), dim3(32, 8)>>>(w_dense, wdenseT_h, 4096, 4096);

    // 1) QKV projection + bias (fp16 mma, fp32 out)
    gemm_h<<<dim3(4608 / 128, 4096 / 128), 256, G_SMEM_BYTES>>>(
        hid_h, wqkvT_h, b_qkv, qkv, 4096, 4608, 4096);

    // 2) rope + fp16 layouts
    {
        int total = 4096 * 34 * 64;
        rope_convert_kernel<<<(total + 255) / 256, 256>>>(qkv, positions, q_h, k_h);
    }
    v_transpose_kernel<<<dim3(64, 8, 2), dim3(32, 8)>>>(qkv, v_t);

    // 3) fp16 mma flash attention
    attn_mma_kernel<<<dim3(16, 32, 2), 256, A_SMEM_BYTES>>>(q_h, k_h, v_t, attn_h);

    // 4) dense projection (fp16 mma, fp32 out)
    gemm_h<<<dim3(4096 / 128, 4096 / 128), 256, G_SMEM_BYTES>>>(
        attn_h, wdenseT_h, nullptr, out, 4096, 4096, 4096);
}

// round 6
// speedup vs baseline: 7.4716x; 1.0774x over previous
#include <cuda_runtime.h>
#include <cuda_fp16.h>
#include <math.h>
#include <stdint.h>

// ---------------- constants ----------------
// B=2, S=2048, H=4096, NH=32, NKV=2, HD=128, ROT=64
// BS=4096 tokens; qkv width 4608 (q:[0,4096) k:[4096,4352) v:[4352,4608))

__device__ __half g_hid_h[(size_t)4096 * 4096];
__device__ __half g_wqkvT_h[(size_t)4608 * 4096];
__device__ __half g_wdenseT_h[(size_t)4096 * 4096];
__device__ __half g_q_h[(size_t)2 * 32 * 2048 * 128];  // [b][h][t][d] rope+scale
__device__ __half g_k_h[(size_t)2 * 2 * 2048 * 128];   // [b][kvh][t][d] rope
__device__ __half g_v_h[(size_t)4096 * 256];           // [tok][dglob]
__device__ __half g_v_t[(size_t)2 * 2 * 128 * 2048];   // [b][kvh][d][t]
__device__ __half g_attn_h[(size_t)4096 * 4096];       // [tok][H]

// ---------------- helpers ----------------
__device__ __forceinline__ uint32_t smem_u32(const void* p) {
    uint32_t a;
    asm("{ .reg .u64 t; cvta.to.shared.u64 t, %1; cvt.u32.u64 %0, t; }" : "=r"(a) : "l"(p));
    return a;
}
__device__ __forceinline__ void cp16(uint32_t s, const void* g) {
    asm volatile("cp.async.cg.shared.global [%0], [%1], 16;" :: "r"(s), "l"(g));
}
__device__ __forceinline__ void mma_f16(float* d, const uint32_t* a, const uint32_t* b) {
    asm volatile(
        "mma.sync.aligned.m16n8k16.row.col.f32.f16.f16.f32 "
        "{%0,%1,%2,%3}, {%4,%5,%6,%7}, {%8,%9}, {%0,%1,%2,%3};"
        : "+f"(d[0]), "+f"(d[1]), "+f"(d[2]), "+f"(d[3])
        : "r"(a[0]), "r"(a[1]), "r"(a[2]), "r"(a[3]), "r"(b[0]), "r"(b[1]));
}
__device__ __forceinline__ void ldsm4(uint32_t* r, uint32_t addr) {
    asm volatile("ldmatrix.sync.aligned.m8n8.x4.shared.b16 {%0,%1,%2,%3}, [%4];"
                 : "=r"(r[0]), "=r"(r[1]), "=r"(r[2]), "=r"(r[3]) : "r"(addr));
}
__device__ __forceinline__ uint32_t packh2(float x, float y) {
    __half2 h = __floats2half2_rn(x, y);
    return *(uint32_t*)&h;
}

// ---------------- fp16 mma GEMM (ldmatrix) ----------------
// CTA 128x128, K-chunk 32 halves, 3 stages, 256 thr, warp tile 32x64.
// smem rows padded to 40 halves (80B) -> conflict-free ldmatrix phases.
// MODE 0: C fp32 (+bias).  MODE 1: fused qkv epilogue (bias+rope+fp16 pack).
#define GS 3
#define STG_H 10240
#define STG_B (STG_H * 2)                 // 20480 bytes/stage
#define G_SMEM_BYTES (GS * STG_B)         // 61440

template <int MODE>
__global__ __launch_bounds__(256, 2)
void gemm_h_t(const __half* __restrict__ A, const __half* __restrict__ Bt,
              const float* __restrict__ bias, float* __restrict__ C,
              __half* __restrict__ qh, __half* __restrict__ kh, __half* __restrict__ vh,
              const int* __restrict__ positions, int M, int N, int K)
{
    extern __shared__ __half sh[];
    const uint32_t sb = smem_u32(sh);
    const int tid = threadIdx.x;
    const int wid = tid >> 5, lane = tid & 31;
    const int grp = lane >> 2, thr = lane & 3;
    const int wm = wid & 3, wn = wid >> 2;
    const int m0 = blockIdx.y * 128, n0 = blockIdx.x * 128;

    const int row = tid >> 1;
    const int off = (tid & 1) * 16;
    const __half* Ap = A + (size_t)(m0 + row) * K + off;
    const __half* Bp = Bt + (size_t)(n0 + row) * K + off;
    const uint32_t sA = sb + (uint32_t)(row * 40 + off) * 2;
    const uint32_t sB = sA + STG_H;   // +5120 halves = +10240 bytes

    auto load_stage = [&](int ch, int st) {
        const uint32_t so = (uint32_t)st * STG_B;
        const __half* a = Ap + ch * 32;
        const __half* b = Bp + ch * 32;
        cp16(sA + so, a);  cp16(sA + so + 16, a + 8);
        cp16(sB + so, b);  cp16(sB + so + 16, b + 8);
        asm volatile("cp.async.commit_group;" ::: "memory");
    };

    float acc[2][8][4];
#pragma unroll
    for (int mt = 0; mt < 2; mt++)
#pragma unroll
        for (int nt = 0; nt < 8; nt++)
#pragma unroll
            for (int j = 0; j < 4; j++) acc[mt][nt][j] = 0.f;

    const int NK = K >> 5;
    load_stage(0, 0);
    load_stage(1, 1);

    // ldmatrix per-lane addresses
    const int lrow = lane & 15;
    const int lcol = (lane >> 4) * 16;   // bytes
    const uint32_t aAddr = sb + (uint32_t)((wm * 32 + lrow) * 40) * 2 + lcol;
    const uint32_t bAddr = sb + 10240 + (uint32_t)((wn * 64 + lrow) * 40) * 2 + lcol;

    int st = 0;
    for (int i = 0; i < NK; i++) {
        asm volatile("cp.async.wait_group %0;" :: "n"(1) : "memory");
        __syncthreads();
        int nxt = i + 2;
        if (nxt < NK) {
            int ns = st + 2; if (ns >= GS) ns -= GS;
            load_stage(nxt, ns);
        } else {
            asm volatile("cp.async.commit_group;" ::: "memory");
        }

        const uint32_t so = (uint32_t)st * STG_B;
#pragma unroll
        for (int kk = 0; kk < 2; kk++) {
            uint32_t a[2][4];
            ldsm4(a[0], aAddr + so + kk * 32);
            ldsm4(a[1], aAddr + so + 16 * 80 + kk * 32);
            uint32_t b[8][2];
#pragma unroll
            for (int ntp = 0; ntp < 4; ntp++) {
                uint32_t tt[4];
                ldsm4(tt, bAddr + so + ntp * (16 * 80) + kk * 32);
                b[2 * ntp][0] = tt[0];  b[2 * ntp][1] = tt[2];
                b[2 * ntp + 1][0] = tt[1];  b[2 * ntp + 1][1] = tt[3];
            }
#pragma unroll
            for (int mt = 0; mt < 2; mt++)
#pragma unroll
                for (int nt = 0; nt < 8; nt++)
                    mma_f16(acc[mt][nt], a[mt], b[nt]);
        }
        st++; if (st == GS) st = 0;
    }

    if (MODE == 0) {
#pragma unroll
        for (int mt = 0; mt < 2; mt++) {
            const int r0 = m0 + wm * 32 + mt * 16 + grp;
#pragma unroll
            for (int nt = 0; nt < 8; nt++) {
                const int col = n0 + wn * 64 + nt * 8 + thr * 2;
                float b0 = 0.f, b1 = 0.f;
                if (bias) { b0 = __ldg(&bias[col]); b1 = __ldg(&bias[col + 1]); }
                *(float2*)&C[(size_t)r0 * N + col] =
                    make_float2(acc[mt][nt][0] + b0, acc[mt][nt][1] + b1);
                *(float2*)&C[(size_t)(r0 + 8) * N + col] =
                    make_float2(acc[mt][nt][2] + b0, acc[mt][nt][3] + b1);
            }
        }
    } else {
        // fused qkv epilogue: bias + rope + fp16 pack into q/k/v layouts
        const int head = n0 >> 7;   // whole CTA tile sits in one 128-wide head
#pragma unroll
        for (int mt = 0; mt < 2; mt++) {
            const int r0 = m0 + wm * 32 + mt * 16 + grp;
#pragma unroll
            for (int rs = 0; rs < 2; rs++) {
                const int r = r0 + rs * 8;
                const int t = r & 2047, bb = r >> 11;
                const float pos = (float)__ldg(&positions[r]);
#pragma unroll
                for (int nt = 0; nt < 8; nt++) {
                    const int col = n0 + wn * 64 + nt * 8 + thr * 2;
                    float v0 = acc[mt][nt][rs * 2] + __ldg(&bias[col]);
                    float v1 = acc[mt][nt][rs * 2 + 1] + __ldg(&bias[col + 1]);
                    const int d = col & 127;
                    if (head < 34) {
                        if (d < 64) {
                            const int pi = d >> 1;
                            float ang = pos * __expf((float)(-pi) * 0.28782313662425572f);
                            float c, s;
                            __sincosf(ang, &s, &c);
                            float o1 = v0 * c - v1 * s;
                            float o2 = v0 * s + v1 * c;
                            v0 = o1; v1 = o2;
                        }
                        if (head < 32) {
                            const float sc = 0.08838834764831845f;
                            uint32_t p = packh2(v0 * sc, v1 * sc);
                            *(uint32_t*)(qh + ((((size_t)(bb * 32 + head)) * 2048 + t) * 128 + d)) = p;
                        } else {
                            uint32_t p = packh2(v0, v1);
                            *(uint32_t*)(kh + ((((size_t)(bb * 2 + head - 32)) * 2048 + t) * 128 + d)) = p;
                        }
                    } else {
                        uint32_t p = packh2(v0, v1);
                        *(uint32_t*)(vh + ((size_t)r * 256 + (col - 4352))) = p;
                    }
                }
            }
        }
    }
}

// ---------------- prep kernels ----------------
__global__ void convert_h_kernel(const float4* __restrict__ src, uint2* __restrict__ dst, int n4)
{
    int i = blockIdx.x * blockDim.x + threadIdx.x;
    if (i >= n4) return;
    float4 v = src[i];
    uint2 o;
    o.x = packh2(v.x, v.y);
    o.y = packh2(v.z, v.w);
    dst[i] = o;
}

// src [R][C] fp32 -> dst [C][R] fp16
__global__ void transpose_h_kernel(const float* __restrict__ src, __half* __restrict__ dst,
                                   int R, int C)
{
    __shared__ float t[32][33];
    int c0 = blockIdx.x * 32, r0 = blockIdx.y * 32;
    int x = threadIdx.x, y = threadIdx.y;
#pragma unroll
    for (int i = 0; i < 32; i += 8)
        t[y + i][x] = src[(size_t)(r0 + y + i) * C + c0 + x];
    __syncthreads();
#pragma unroll
    for (int i = 0; i < 32; i += 8)
        dst[(size_t)(c0 + y + i) * R + r0 + x] = __float2half(t[x][y + i]);
}

// vh [b*2048+t][256] -> vt [b*256+dg][2048]  (fp16)
__global__ void v_transpose_h_kernel(const __half* __restrict__ vh, __half* __restrict__ vt)
{
    __shared__ __half t[32][33];
    int t0 = blockIdx.x * 32, d0 = blockIdx.y * 32, b = blockIdx.z;
    int x = threadIdx.x, y = threadIdx.y;
#pragma unroll
    for (int i = 0; i < 32; i += 8)
        t[y + i][x] = vh[(size_t)(b * 2048 + t0 + y + i) * 256 + d0 + x];
    __syncthreads();
#pragma unroll
    for (int i = 0; i < 32; i += 8)
        vt[(size_t)(b * 256 + d0 + y + i) * 2048 + t0 + x] = t[x][y + i];
}

// ---------------- fp16 mma flash attention (ldmatrix) ----------------
#define AQ_ST 136
#define AK_ST 136
#define AV_ST 72
#define SQ_OFF 0
#define SK_OFF (128 * AQ_ST)
#define SV_OFF (SK_OFF + 2 * 64 * AK_ST)
#define A_SMEM_HALVES (SV_OFF + 2 * 128 * AV_ST)
#define A_SMEM_BYTES (A_SMEM_HALVES * 2)   // 106496

__global__ __launch_bounds__(256, 1)
void attn_mma_kernel(const __half* __restrict__ qh, const __half* __restrict__ kh,
                     const __half* __restrict__ vt, __half* __restrict__ out)
{
    extern __shared__ __half sa[];
    const uint32_t sb = smem_u32(sa);
    const int tid = threadIdx.x;
    const int w = tid >> 5, lane = tid & 31;
    const int grp = lane >> 2, thr = lane & 3;
    const int qt = 15 - blockIdx.x;
    const int h = blockIdx.y, b = blockIdx.z;
    const int kvh = h >> 4;

    const __half* Qg = qh + (((size_t)(b * 32 + h)) * 2048 + qt * 128) * 128;
    const __half* Kg = kh + ((size_t)(b * 2 + kvh)) * 2048 * 128;
    const __half* Vg = vt + ((size_t)(b * 2 + kvh)) * 128 * 2048;

    {
        int r = tid >> 1;
        int s0 = (tid & 1) * 8;
        const __half* src = Qg + r * 128 + s0 * 8;
        uint32_t dst = sb + (uint32_t)(SQ_OFF + r * AQ_ST + s0 * 8) * 2;
#pragma unroll
        for (int j = 0; j < 8; j++) cp16(dst + j * 16, src + j * 8);
    }
    auto load_kv = [&](int kt, int buf) {
        {
            int r = tid >> 2;
            int s0 = (tid & 3) * 4;
            const __half* src = Kg + ((size_t)(kt * 64 + r)) * 128 + s0 * 8;
            uint32_t dst = sb + (uint32_t)(SK_OFF + buf * 64 * AK_ST + r * AK_ST + s0 * 8) * 2;
#pragma unroll
            for (int j = 0; j < 4; j++) cp16(dst + j * 16, src + j * 8);
        }
        {
            int r = tid >> 1;
            int s0 = (tid & 1) * 4;
            const __half* src = Vg + (size_t)r * 2048 + kt * 64 + s0 * 8;
            uint32_t dst = sb + (uint32_t)(SV_OFF + buf * 128 * AV_ST + r * AV_ST + s0 * 8) * 2;
#pragma unroll
            for (int j = 0; j < 4; j++) cp16(dst + j * 16, src + j * 8);
        }
    };

    const int NT = 2 * qt + 2;
    load_kv(0, 0);
    asm volatile("cp.async.commit_group;" ::: "memory");

    float o[16][4];
#pragma unroll
    for (int nt = 0; nt < 16; nt++)
#pragma unroll
        for (int j = 0; j < 4; j++) o[nt][j] = 0.f;
    float m1 = -1e30f, m2 = -1e30f, l1 = 0.f, l2 = 0.f;

    const int qr1 = qt * 128 + w * 16 + grp;
    const int qr2 = qr1 + 8;
    const int wr_max = qt * 128 + w * 16 + 15;

    // ldmatrix per-lane bases
    const int lrow = lane & 15;
    const int lcol = (lane >> 4) * 16;   // bytes
    const uint32_t qAddr = sb + (uint32_t)(SQ_OFF + (w * 16 + lrow) * AQ_ST) * 2 + lcol;
    const uint32_t kAddr0 = sb + (uint32_t)(SK_OFF + lrow * AK_ST) * 2 + lcol;
    const uint32_t vAddr0 = sb + (uint32_t)(SV_OFF + lrow * AV_ST) * 2 + lcol;

    for (int kt = 0; kt < NT; kt++) {
        if (kt + 1 < NT) load_kv(kt + 1, (kt + 1) & 1);
        asm volatile("cp.async.commit_group;" ::: "memory");
        asm volatile("cp.async.wait_group 1;" ::: "memory");
        __syncthreads();

        const bool active = (kt * 64 <= wr_max);
        if (active) {
            const uint32_t kA = kAddr0 + (uint32_t)((kt & 1) * 64 * AK_ST) * 2;
            const uint32_t vA = vAddr0 + (uint32_t)((kt & 1) * 128 * AV_ST) * 2;

            float sc[8][4];
#pragma unroll
            for (int nt = 0; nt < 8; nt++)
#pragma unroll
                for (int j = 0; j < 4; j++) sc[nt][j] = 0.f;

#pragma unroll
            for (int kk = 0; kk < 8; kk++) {
                uint32_t aq[4];
                ldsm4(aq, qAddr + kk * 32);
#pragma unroll
                for (int ntp = 0; ntp < 4; ntp++) {
                    uint32_t tt[4];
                    ldsm4(tt, kA + ntp * (16 * AK_ST * 2) + kk * 32);
                    uint32_t b0[2] = {tt[0], tt[2]};
                    uint32_t b1[2] = {tt[1], tt[3]};
                    mma_f16(sc[2 * ntp], aq, b0);
                    mma_f16(sc[2 * ntp + 1], aq, b1);
                }
            }

            if (kt * 64 + 63 > qt * 128 + w * 16) {
#pragma unroll
                for (int nt = 0; nt < 8; nt++) {
                    int c0 = kt * 64 + nt * 8 + thr * 2;
                    if (c0 > qr1) sc[nt][0] = -1e30f;
                    if (c0 + 1 > qr1) sc[nt][1] = -1e30f;
                    if (c0 > qr2) sc[nt][2] = -1e30f;
                    if (c0 + 1 > qr2) sc[nt][3] = -1e30f;
                }
            }

            float rm1 = -1e30f, rm2 = -1e30f;
#pragma unroll
            for (int nt = 0; nt < 8; nt++) {
                rm1 = fmaxf(rm1, fmaxf(sc[nt][0], sc[nt][1]));
                rm2 = fmaxf(rm2, fmaxf(sc[nt][2], sc[nt][3]));
            }
            rm1 = fmaxf(rm1, __shfl_xor_sync(0xffffffffu, rm1, 1));
            rm1 = fmaxf(rm1, __shfl_xor_sync(0xffffffffu, rm1, 2));
            rm2 = fmaxf(rm2, __shfl_xor_sync(0xffffffffu, rm2, 1));
            rm2 = fmaxf(rm2, __shfl_xor_sync(0xffffffffu, rm2, 2));

            float mn1 = fmaxf(m1, rm1), mn2 = fmaxf(m2, rm2);
            float f1 = __expf(m1 - mn1), f2 = __expf(m2 - mn2);
            m1 = mn1; m2 = mn2;

            uint32_t pf[8][2];
            float s1 = 0.f, s2 = 0.f;
#pragma unroll
            for (int nt = 0; nt < 8; nt++) {
                float e0 = __expf(sc[nt][0] - mn1);
                float e1 = __expf(sc[nt][1] - mn1);
                float e2 = __expf(sc[nt][2] - mn2);
                float e3 = __expf(sc[nt][3] - mn2);
                s1 += e0 + e1; s2 += e2 + e3;
                pf[nt][0] = packh2(e0, e1);
                pf[nt][1] = packh2(e2, e3);
            }
            l1 = l1 * f1 + s1;
            l2 = l2 * f2 + s2;

#pragma unroll
            for (int nt = 0; nt < 16; nt++) {
                o[nt][0] *= f1; o[nt][1] *= f1;
                o[nt][2] *= f2; o[nt][3] *= f2;
            }

#pragma unroll
            for (int kk = 0; kk < 4; kk++) {
                uint32_t ap[4] = {pf[2 * kk][0], pf[2 * kk][1],
                                  pf[2 * kk + 1][0], pf[2 * kk + 1][1]};
#pragma unroll
                for (int ntdp = 0; ntdp < 8; ntdp++) {
                    uint32_t tt[4];
                    ldsm4(tt, vA + ntdp * (16 * AV_ST * 2) + kk * 32);
                    uint32_t b0[2] = {tt[0], tt[2]};
                    uint32_t b1[2] = {tt[1], tt[3]};
                    mma_f16(o[2 * ntdp], ap, b0);
                    mma_f16(o[2 * ntdp + 1], ap, b1);
                }
            }
        }
        __syncthreads();
    }

    l1 += __shfl_xor_sync(0xffffffffu, l1, 1);
    l1 += __shfl_xor_sync(0xffffffffu, l1, 2);
    l2 += __shfl_xor_sync(0xffffffffu, l2, 1);
    l2 += __shfl_xor_sync(0xffffffffu, l2, 2);
    float inv1 = 1.f / l1, inv2 = 1.f / l2;

    const int row1 = b * 2048 + qr1;
    const int row2 = b * 2048 + qr2;
#pragma unroll
    for (int ntd = 0; ntd < 16; ntd++) {
        int col = h * 128 + ntd * 8 + thr * 2;
        *(uint32_t*)(out + (size_t)row1 * 4096 + col) = packh2(o[ntd][0] * inv1, o[ntd][1] * inv1);
        *(uint32_t*)(out + (size_t)row2 * 4096 + col) = packh2(o[ntd][2] * inv2, o[ntd][3] * inv2);
    }
}

// ---------------- launch ----------------
extern "C" void kernel_launch(void* const* d_in, const int* in_sizes, int n_in,
                              void* d_out, int out_size)
{
    const float* hidden    = (const float*)d_in[0];
    const float* w_qkv     = (const float*)d_in[1];
    const float* b_qkv     = (const float*)d_in[2];
    const float* w_dense   = (const float*)d_in[3];
    const int*   positions = (const int*)d_in[4];
    float* out = (float*)d_out;

    __half *hid_h, *wqkvT_h, *wdenseT_h, *q_h, *k_h, *v_h, *v_t, *attn_h;
    cudaGetSymbolAddress((void**)&hid_h, g_hid_h);
    cudaGetSymbolAddress((void**)&wqkvT_h, g_wqkvT_h);
    cudaGetSymbolAddress((void**)&wdenseT_h, g_wdenseT_h);
    cudaGetSymbolAddress((void**)&q_h, g_q_h);
    cudaGetSymbolAddress((void**)&k_h, g_k_h);
    cudaGetSymbolAddress((void**)&v_h, g_v_h);
    cudaGetSymbolAddress((void**)&v_t, g_v_t);
    cudaGetSymbolAddress((void**)&attn_h, g_attn_h);

    cudaFuncSetAttribute(gemm_h_t<0>, cudaFuncAttributeMaxDynamicSharedMemorySize, G_SMEM_BYTES);
    cudaFuncSetAttribute(gemm_h_t<1>, cudaFuncAttributeMaxDynamicSharedMemorySize, G_SMEM_BYTES);
    cudaFuncSetAttribute(attn_mma_kernel, cudaFuncAttributeMaxDynamicSharedMemorySize,
                         A_SMEM_BYTES);

    // prep
    {
        int n4 = 4096 * 4096 / 4;
        convert_h_kernel<<<(n4 + 255) / 256, 256>>>((const float4*)hidden, (uint2*)hid_h, n4);
    }
    transpose_h_kernel<<<dim3(4608 / 32, 4096 / 32), dim3(32, 8)>>>(w_qkv, wqkvT_h, 4096, 4608);
    transpose_h_kernel<<<dim3(4096 / 32, 4096 / 32), dim3(32, 8)>>>(w_dense, wdenseT_h, 4096, 4096);

    // 1) QKV gemm with fused bias+rope+pack epilogue
    gemm_h_t<1><<<dim3(4608 / 128, 4096 / 128), 256, G_SMEM_BYTES>>>(
        hid_h, wqkvT_h, b_qkv, nullptr, q_h, k_h, v_h, positions, 4096, 4608, 4096);

    // 2) V transpose (fp16)
    v_transpose_h_kernel<<<dim3(64, 8, 2), dim3(32, 8)>>>(v_h, v_t);

    // 3) flash attention
    attn_mma_kernel<<<dim3(16, 32, 2), 256, A_SMEM_BYTES>>>(q_h, k_h, v_t, attn_h);

    // 4) dense projection
    gemm_h_t<0><<<dim3(4096 / 128, 4096 / 128), 256, G_SMEM_BYTES>>>(
        attn_h, wdenseT_h, nullptr, out, nullptr, nullptr, nullptr, nullptr, 4096, 4096, 4096);
}